// round 5
// baseline (speedup 1.0000x reference)
#include <cuda_runtime.h>

#define BB 16
#define NN 1024
#define MM 12
#define FA 128
#define FO 128

#define ROWS_PER_BLK 64
#define US 68   // sU row stride in floats (padded: [k][r], 64 rows + 4 pad)

// Scratch (allocation-free rule: __device__ globals)
__device__ float g_bn3[BB * NN];
__device__ float g_bn6[BB * NN];
__device__ int   g_is64;

// ---------------------------------------------------------------------------
// Kernel 1: per-(b,n) bond norm chain up to the M-product -> g_bn3
// One warp handles two (b,n) rows: half-warp per row, lane lm<12 owns one m.
// Warp 0 of block 0 additionally sniffs the adj dtype (int32 vs int64).
// ---------------------------------------------------------------------------
__global__ void bond_kernel(const float* __restrict__ bond,
                            const int* __restrict__ adj_raw) {
    // ---- dtype sniff: int64 indices < 1024 have all-zero odd 32-bit words
    if (blockIdx.x == 0 && threadIdx.x < 32) {
        int lane = threadIdx.x;
        bool odd_zero = true;
        #pragma unroll
        for (int j = 0; j < 32; j++) {
            int pair = lane + 32 * j;            // first 1024 pairs
            if (adj_raw[2 * pair + 1] != 0) odd_zero = false;
        }
        bool all = __all_sync(0xffffffffu, odd_zero);
        if (lane == 0) g_is64 = all ? 1 : 0;
    }

    int warp = (blockIdx.x * blockDim.x + threadIdx.x) >> 5;
    int lane = threadIdx.x & 31;
    int half = lane >> 4;
    int lm   = lane & 15;
    int row  = warp * 2 + half;          // row = b*NN + n
    if (row >= BB * NN) return;

    float ssq = 0.0f;
    if (lm < MM) {
        const float4* p = (const float4*)(bond + (size_t)row * (MM * 32) + lm * 32);
        #pragma unroll
        for (int i = 0; i < 8; i++) {
            float4 v = p[i];
            ssq += v.x * v.x + v.y * v.y + v.z * v.z + v.w * v.w;
        }
    }
    // bond_norm = sqrt(ssq); bond_norm**(-2) == 1/ssq
    float x = (lm < MM) ? (1.0f / ssq) : 0.0f;

    // half-warp (width 16) sum over m
    float s = x;
    #pragma unroll
    for (int o = 8; o >= 1; o >>= 1) s += __shfl_xor_sync(0xffffffffu, s, o, 16);
    s = fmaxf(s, 1e-12f);

    // half-warp product of normalized values (idle lanes contribute 1)
    float t = (lm < MM) ? (x / s) : 1.0f;
    #pragma unroll
    for (int o = 8; o >= 1; o >>= 1) t *= __shfl_xor_sync(0xffffffffu, t, o, 16);

    if (lm == 0) g_bn3[row] = t;
}

// ---------------------------------------------------------------------------
// Kernel 2: normalize over B (axis 0), invert, normalize over N (axis 1).
// ---------------------------------------------------------------------------
__global__ void norm_kernel() {
    int b = blockIdx.x;
    int n = threadIdx.x;

    float csum = 0.0f;
    #pragma unroll
    for (int bb = 0; bb < BB; bb++) csum += fabsf(g_bn3[bb * NN + n]);
    csum = fmaxf(csum, 1e-12f);

    float bn4 = g_bn3[b * NN + n] / csum;
    float bn5 = 1.0f / bn4;

    // block-wide sum of |bn5| over n (1024 threads)
    float r = fabsf(bn5);
    #pragma unroll
    for (int o = 16; o >= 1; o >>= 1) r += __shfl_xor_sync(0xffffffffu, r, o, 32);

    __shared__ float part[32];
    __shared__ float total;
    int wid = threadIdx.x >> 5, lane = threadIdx.x & 31;
    if (lane == 0) part[wid] = r;
    __syncthreads();
    if (wid == 0) {
        float v = part[lane];
        #pragma unroll
        for (int o = 16; o >= 1; o >>= 1) v += __shfl_xor_sync(0xffffffffu, v, o, 32);
        if (lane == 0) total = fmaxf(v, 1e-12f);
    }
    __syncthreads();

    g_bn6[b * NN + n] = bn5 / total;
}

// ---------------------------------------------------------------------------
// Kernel 3: gather + scale + fp32 GEMM (u @ W + bias, relu)
// Block = 64 rows x 128 cols, 128 threads.
// Phase A: u rows -> smem TRANSPOSED as sU[k][r] (k-major, padded stride).
// Phase B: classic register tiling, 8 rows x 8 cols per thread, scalar FFMA.
// ---------------------------------------------------------------------------
__global__ void __launch_bounds__(128, 2)
main_kernel(const float* __restrict__ atom,
            const int* __restrict__ adj,
            const float* __restrict__ W,
            const float* __restrict__ bias,
            float* __restrict__ out) {
    extern __shared__ float smem[];
    float* sW = smem;                    // 128*128 floats = 64 KB (row-major W[k][j])
    float* sU = smem + FA * FO;          // [k=128][r=64] stride US -> 34.8 KB

    int b   = blockIdx.y;
    int n0  = blockIdx.x * ROWS_PER_BLK;
    int tid = threadIdx.x;
    int stride = g_is64 ? 2 : 1;         // int64 -> read low words, stride 2

    // Load W into smem, coalesced float4
    {
        const float4* Wg = (const float4*)W;
        float4* sW4 = (float4*)sW;
        for (int i = tid; i < (FA * FO) / 4; i += 128) sW4[i] = Wg[i];
    }

    // ---- Phase A: u = (atom_row + mean_m atom[adj]) * bn6, store transposed
    {
        int wid = tid >> 5, lane = tid & 31;
        const float* atomB = atom + b * NN * FA;
        #pragma unroll
        for (int i = 0; i < 16; i++) {
            int r = wid * 16 + i;
            int n = n0 + r;
            const int* adjr = adj + (size_t)(b * NN + n) * MM * stride;
            float4 a4 = *(const float4*)(atomB + n * FA + lane * 4);
            float sx = 0.f, sy = 0.f, sz = 0.f, sw = 0.f;
            #pragma unroll
            for (int m = 0; m < MM; m++) {
                int idx = adjr[m * stride] & (NN - 1);
                float4 v = *(const float4*)(atomB + idx * FA + lane * 4);
                sx += v.x; sy += v.y; sz += v.z; sw += v.w;
            }
            float sc = g_bn6[b * NN + n];
            const float inv12 = 1.0f / 12.0f;
            int k = lane * 4;
            sU[(k + 0) * US + r] = (a4.x + sx * inv12) * sc;
            sU[(k + 1) * US + r] = (a4.y + sy * inv12) * sc;
            sU[(k + 2) * US + r] = (a4.z + sz * inv12) * sc;
            sU[(k + 3) * US + r] = (a4.w + sw * inv12) * sc;
        }
    }
    __syncthreads();

    // ---- Phase B: 8 rows x 8 cols per thread, scalar FFMA
    int ty = tid >> 4;        // 0..7  -> rows [ty*8, ty*8+8)
    int tx = tid & 15;        // 0..15 -> cols [tx*8, tx*8+8)
    int r0 = ty * 8;
    int c0 = tx * 8;

    float acc[8][8];
    #pragma unroll
    for (int i = 0; i < 8; i++)
        #pragma unroll
        for (int j = 0; j < 8; j++) acc[i][j] = 0.0f;

    #pragma unroll 2
    for (int k = 0; k < FA; k++) {
        float4 w0 = *(const float4*)(sW + k * FO + c0);
        float4 w1 = *(const float4*)(sW + k * FO + c0 + 4);
        float4 ua = *(const float4*)(sU + k * US + r0);
        float4 ub = *(const float4*)(sU + k * US + r0 + 4);
        float ur[8] = {ua.x, ua.y, ua.z, ua.w, ub.x, ub.y, ub.z, ub.w};
        float wc[8] = {w0.x, w0.y, w0.z, w0.w, w1.x, w1.y, w1.z, w1.w};
        #pragma unroll
        for (int i = 0; i < 8; i++)
            #pragma unroll
            for (int j = 0; j < 8; j++)
                acc[i][j] = fmaf(ur[i], wc[j], acc[i][j]);
    }

    // Epilogue: bias + relu + float4 stores
    float4 b0 = *(const float4*)(bias + c0);
    float4 b1 = *(const float4*)(bias + c0 + 4);
    float bc[8] = {b0.x, b0.y, b0.z, b0.w, b1.x, b1.y, b1.z, b1.w};

    #pragma unroll
    for (int i = 0; i < 8; i++) {
        int n = n0 + r0 + i;
        float4 o0, o1;
        o0.x = fmaxf(acc[i][0] + bc[0], 0.0f);
        o0.y = fmaxf(acc[i][1] + bc[1], 0.0f);
        o0.z = fmaxf(acc[i][2] + bc[2], 0.0f);
        o0.w = fmaxf(acc[i][3] + bc[3], 0.0f);
        o1.x = fmaxf(acc[i][4] + bc[4], 0.0f);
        o1.y = fmaxf(acc[i][5] + bc[5], 0.0f);
        o1.z = fmaxf(acc[i][6] + bc[6], 0.0f);
        o1.w = fmaxf(acc[i][7] + bc[7], 0.0f);
        float* op = out + (size_t)(b * NN + n) * FO + c0;
        *(float4*)(op)     = o0;
        *(float4*)(op + 4) = o1;
    }
}

// ---------------------------------------------------------------------------
extern "C" void kernel_launch(void* const* d_in, const int* in_sizes, int n_in,
                              void* d_out, int out_size) {
    const float* atom = (const float*)d_in[0];
    const float* bond = (const float*)d_in[1];
    const int*   adj  = (const int*)d_in[2];
    const float* W    = (const float*)d_in[3];
    const float* bias = (const float*)d_in[4];
    float*       out  = (float*)d_out;

    // 8192 warps x 2 rows per warp = 16384 rows = BB*NN  (R2 bug: was 512 blocks)
    bond_kernel<<<1024, 256>>>(bond, adj);
    norm_kernel<<<BB, NN>>>();

    const int smem_bytes = (FA * FO) * 4 + FA * US * 4;  // 64KB + 34.8KB
    cudaFuncSetAttribute(main_kernel, cudaFuncAttributeMaxDynamicSharedMemorySize,
                         smem_bytes);
    main_kernel<<<dim3(NN / ROWS_PER_BLK, BB), 128, smem_bytes>>>(atom, adj, W, bias, out);
}

// round 6
// speedup vs baseline: 1.0628x; 1.0628x over previous
#include <cuda_runtime.h>

#define BB 16
#define NN 1024
#define MM 12
#define FA 128
#define FO 128

#define ROWS_PER_BLK 64
#define US 68   // sU row stride in floats (padded: [k][r], 64 rows + 4 pad)

// Scratch (allocation-free rule: __device__ globals)
__device__ float g_bn3[BB * NN];
__device__ float g_bn6[BB * NN];
__device__ int   g_is64;

// ---------------------------------------------------------------------------
// packed f32x2 helpers
// ---------------------------------------------------------------------------
__device__ __forceinline__ void fma2(unsigned long long& d,
                                     unsigned long long a,
                                     unsigned long long b) {
    asm("fma.rn.f32x2 %0, %1, %2, %0;" : "+l"(d) : "l"(a), "l"(b));
}
__device__ __forceinline__ unsigned long long dup2(float v) {
    unsigned long long r;
    asm("mov.b64 %0, {%1, %1};" : "=l"(r) : "f"(v));
    return r;
}
__device__ __forceinline__ float2 unpack2(unsigned long long v) {
    float2 r;
    asm("mov.b64 {%0, %1}, %2;" : "=f"(r.x), "=f"(r.y) : "l"(v));
    return r;
}

// ---------------------------------------------------------------------------
// Kernel 1 (v2): one warp per (b,n) row, fully coalesced loads.
// Row = 12*32 floats = 96 float4 = 3 warp-wide LDG.128.
// chunk c (float4 #c) belongs to m = c>>3. Lane's 3 chunks: lane, lane+32,
// lane+64 -> m = lane>>3, 4+lane>>3, 8+lane>>3.
// Width-8 shfl reduce gives per-m ssq; cross-group shfl gives sum/product.
// prod_m(x_m / s) == (prod x_m) / s^12.
// ---------------------------------------------------------------------------
__global__ void bond_kernel(const float* __restrict__ bond,
                            const int* __restrict__ adj_raw) {
    // ---- dtype sniff: int64 indices < 1024 have all-zero odd 32-bit words
    if (blockIdx.x == 0 && threadIdx.x < 32) {
        int lane = threadIdx.x;
        bool odd_zero = true;
        #pragma unroll
        for (int j = 0; j < 32; j++) {
            int pair = lane + 32 * j;
            if (adj_raw[2 * pair + 1] != 0) odd_zero = false;
        }
        bool all = __all_sync(0xffffffffu, odd_zero);
        if (lane == 0) g_is64 = all ? 1 : 0;
    }

    int warp = (blockIdx.x * blockDim.x + threadIdx.x) >> 5;
    int lane = threadIdx.x & 31;
    if (warp >= BB * NN) return;

    const float4* p = (const float4*)(bond + (size_t)warp * (MM * 32));
    float4 v0 = p[lane];
    float4 v1 = p[lane + 32];
    float4 v2 = p[lane + 64];
    float q0 = v0.x * v0.x + v0.y * v0.y + v0.z * v0.z + v0.w * v0.w;
    float q1 = v1.x * v1.x + v1.y * v1.y + v1.z * v1.z + v1.w * v1.w;
    float q2 = v2.x * v2.x + v2.y * v2.y + v2.z * v2.z + v2.w * v2.w;

    // reduce within groups of 8 lanes (one m per group per load slot)
    #pragma unroll
    for (int o = 4; o >= 1; o >>= 1) {
        q0 += __shfl_xor_sync(0xffffffffu, q0, o, 8);
        q1 += __shfl_xor_sync(0xffffffffu, q1, o, 8);
        q2 += __shfl_xor_sync(0xffffffffu, q2, o, 8);
    }
    // x_m = bond_norm^-2 = 1/ssq
    float x0 = 1.0f / q0, x1 = 1.0f / q1, x2 = 1.0f / q2;

    // cross-group (offsets 8,16): sum over all 12 m, product over all 12 m
    float s = x0 + x1 + x2;
    float pr = x0 * x1 * x2;
    s  += __shfl_xor_sync(0xffffffffu, s, 8);
    s  += __shfl_xor_sync(0xffffffffu, s, 16);
    pr *= __shfl_xor_sync(0xffffffffu, pr, 8);
    pr *= __shfl_xor_sync(0xffffffffu, pr, 16);

    s = fmaxf(s, 1e-12f);
    float s2 = s * s, s4 = s2 * s2, s8 = s4 * s4;
    float t = pr / (s8 * s4);

    if (lane == 0) g_bn3[warp] = t;
}

// ---------------------------------------------------------------------------
// Kernel 2: normalize over B (axis 0), invert, normalize over N (axis 1).
// ---------------------------------------------------------------------------
__global__ void norm_kernel() {
    int b = blockIdx.x;
    int n = threadIdx.x;

    float csum = 0.0f;
    #pragma unroll
    for (int bb = 0; bb < BB; bb++) csum += fabsf(g_bn3[bb * NN + n]);
    csum = fmaxf(csum, 1e-12f);

    float bn4 = g_bn3[b * NN + n] / csum;
    float bn5 = 1.0f / bn4;

    float r = fabsf(bn5);
    #pragma unroll
    for (int o = 16; o >= 1; o >>= 1) r += __shfl_xor_sync(0xffffffffu, r, o, 32);

    __shared__ float part[32];
    __shared__ float total;
    int wid = threadIdx.x >> 5, lane = threadIdx.x & 31;
    if (lane == 0) part[wid] = r;
    __syncthreads();
    if (wid == 0) {
        float v = part[lane];
        #pragma unroll
        for (int o = 16; o >= 1; o >>= 1) v += __shfl_xor_sync(0xffffffffu, v, o, 32);
        if (lane == 0) total = fmaxf(v, 1e-12f);
    }
    __syncthreads();

    g_bn6[b * NN + n] = bn5 / total;
}

// ---------------------------------------------------------------------------
// Kernel 3: gather + scale + fp32 GEMM (u @ W + bias, relu)
// Block = 64 rows x 128 cols, 128 threads, occ 2.
// Phase A: u rows -> smem TRANSPOSED as sU[k][r].
// Phase B: 8 rows x 8 cols per thread; cols processed as 4 packed pairs via
// fma.rn.f32x2 (32 FFMA2/k instead of 64 FFMA). u duplicated into a register
// pair with one ALU-pipe mov.b64 per row.
// ---------------------------------------------------------------------------
__global__ void __launch_bounds__(128, 2)
main_kernel(const float* __restrict__ atom,
            const int* __restrict__ adj,
            const float* __restrict__ W,
            const float* __restrict__ bias,
            float* __restrict__ out) {
    extern __shared__ float smem[];
    float* sW = smem;                    // 128*128 floats = 64 KB (row-major W[k][j])
    float* sU = smem + FA * FO;          // [k=128][r=64] stride US -> 34.8 KB

    int b   = blockIdx.y;
    int n0  = blockIdx.x * ROWS_PER_BLK;
    int tid = threadIdx.x;
    int stride = g_is64 ? 2 : 1;         // int64 -> read low words, stride 2

    // Load W into smem, coalesced float4
    {
        const float4* Wg = (const float4*)W;
        float4* sW4 = (float4*)sW;
        for (int i = tid; i < (FA * FO) / 4; i += 128) sW4[i] = Wg[i];
    }

    // ---- Phase A: u = (atom_row + mean_m atom[adj]) * bn6, store transposed
    {
        int wid = tid >> 5, lane = tid & 31;
        const float* atomB = atom + b * NN * FA;
        #pragma unroll
        for (int i = 0; i < 16; i++) {
            int r = wid * 16 + i;
            int n = n0 + r;
            const int* adjr = adj + (size_t)(b * NN + n) * MM * stride;
            float4 a4 = *(const float4*)(atomB + n * FA + lane * 4);
            float sx = 0.f, sy = 0.f, sz = 0.f, sw = 0.f;
            #pragma unroll
            for (int m = 0; m < MM; m++) {
                int idx = adjr[m * stride] & (NN - 1);
                float4 v = *(const float4*)(atomB + idx * FA + lane * 4);
                sx += v.x; sy += v.y; sz += v.z; sw += v.w;
            }
            float sc = g_bn6[b * NN + n];
            const float inv12 = 1.0f / 12.0f;
            int k = lane * 4;
            sU[(k + 0) * US + r] = (a4.x + sx * inv12) * sc;
            sU[(k + 1) * US + r] = (a4.y + sy * inv12) * sc;
            sU[(k + 2) * US + r] = (a4.z + sz * inv12) * sc;
            sU[(k + 3) * US + r] = (a4.w + sw * inv12) * sc;
        }
    }
    __syncthreads();

    // ---- Phase B: 8 rows x (4 col-pairs) per thread, FFMA2
    int ty = tid >> 4;        // 0..7  -> rows [ty*8, ty*8+8)  (2 per warp -> bcast)
    int tx = tid & 15;        // 0..15 -> cols [tx*8, tx*8+8)  (w depends on tx only)
    int r0 = ty * 8;
    int c0 = tx * 8;

    unsigned long long acc[8][4];
    #pragma unroll
    for (int i = 0; i < 8; i++)
        #pragma unroll
        for (int j = 0; j < 4; j++) acc[i][j] = 0ull;

    #pragma unroll 2
    for (int k = 0; k < FA; k++) {
        // w: 8 cols = 4 packed pairs, read directly as 64-bit lanes
        ulonglong2 wa = *(const ulonglong2*)(sW + k * FO + c0);
        ulonglong2 wb = *(const ulonglong2*)(sW + k * FO + c0 + 4);
        // u: 8 rows
        float4 ua = *(const float4*)(sU + k * US + r0);
        float4 ub = *(const float4*)(sU + k * US + r0 + 4);
        unsigned long long uu[8];
        uu[0] = dup2(ua.x); uu[1] = dup2(ua.y); uu[2] = dup2(ua.z); uu[3] = dup2(ua.w);
        uu[4] = dup2(ub.x); uu[5] = dup2(ub.y); uu[6] = dup2(ub.z); uu[7] = dup2(ub.w);
        #pragma unroll
        for (int i = 0; i < 8; i++) {
            fma2(acc[i][0], uu[i], wa.x);
            fma2(acc[i][1], uu[i], wa.y);
            fma2(acc[i][2], uu[i], wb.x);
            fma2(acc[i][3], uu[i], wb.y);
        }
    }

    // Epilogue: bias + relu + float4 stores
    float4 b0 = *(const float4*)(bias + c0);
    float4 b1 = *(const float4*)(bias + c0 + 4);

    #pragma unroll
    for (int i = 0; i < 8; i++) {
        int n = n0 + r0 + i;
        float2 p0 = unpack2(acc[i][0]);
        float2 p1 = unpack2(acc[i][1]);
        float2 p2 = unpack2(acc[i][2]);
        float2 p3 = unpack2(acc[i][3]);
        float4 o0, o1;
        o0.x = fmaxf(p0.x + b0.x, 0.0f);
        o0.y = fmaxf(p0.y + b0.y, 0.0f);
        o0.z = fmaxf(p1.x + b0.z, 0.0f);
        o0.w = fmaxf(p1.y + b0.w, 0.0f);
        o1.x = fmaxf(p2.x + b1.x, 0.0f);
        o1.y = fmaxf(p2.y + b1.y, 0.0f);
        o1.z = fmaxf(p3.x + b1.z, 0.0f);
        o1.w = fmaxf(p3.y + b1.w, 0.0f);
        float* op = out + (size_t)(b * NN + n) * FO + c0;
        *(float4*)(op)     = o0;
        *(float4*)(op + 4) = o1;
    }
}

// ---------------------------------------------------------------------------
extern "C" void kernel_launch(void* const* d_in, const int* in_sizes, int n_in,
                              void* d_out, int out_size) {
    const float* atom = (const float*)d_in[0];
    const float* bond = (const float*)d_in[1];
    const int*   adj  = (const int*)d_in[2];
    const float* W    = (const float*)d_in[3];
    const float* bias = (const float*)d_in[4];
    float*       out  = (float*)d_out;

    // one warp per row: 16384 warps = 2048 blocks x 8 warps
    bond_kernel<<<2048, 256>>>(bond, adj);
    norm_kernel<<<BB, NN>>>();

    const int smem_bytes = (FA * FO) * 4 + FA * US * 4;  // 64KB + 34.8KB
    cudaFuncSetAttribute(main_kernel, cudaFuncAttributeMaxDynamicSharedMemorySize,
                         smem_bytes);
    main_kernel<<<dim3(NN / ROWS_PER_BLK, BB), 128, smem_bytes>>>(atom, adj, W, bias, out);
}